// round 2
// baseline (speedup 1.0000x reference)
#include <cuda_runtime.h>
#include <cstdint>

// Problem constants (fixed by the dataset)
#define NN    8192          // num nodes
#define HH    16            // gru units
#define BB    4             // batch
#define COLS  (BB * HH)     // 64 columns per matrix

// Scratch: gated per-node feature tables, laid out m-major so that a warp
// reads pm[m*64 + lane] / pm[m*64 + lane + 32] as two 128B transactions.
// 2 MB each -> stays L2-resident during the SpMM stream.
__device__ float g_pm[NN * COLS];
__device__ float g_pv[NN * COLS];

// ---------------------------------------------------------------------------
// Kernel A: gating. One thread per (b, n). Computes
//   cm = relu([x*iwm, h_mean] @ Wm + bm)
//   cv = relu([x*iwv, h_var ] @ Wv + bv)
//   nw = exp(-cv);  pm = cm*nw;  pv = cv*nw*nw
// ---------------------------------------------------------------------------
__global__ void rtgcn_gate_kernel(const float* __restrict__ inputs,
                                  const float* __restrict__ hidden,
                                  const float* __restrict__ Wm,
                                  const float* __restrict__ bm,
                                  const float* __restrict__ Wv,
                                  const float* __restrict__ bv,
                                  const float* __restrict__ iwm,
                                  const float* __restrict__ iwv) {
    __shared__ float sWm[17 * 16];
    __shared__ float sWv[17 * 16];
    __shared__ float sbm[16];
    __shared__ float sbv[16];

    int t = threadIdx.x;
    // FIX: 17*16 = 272 > blockDim (256) — must stride the cooperative load.
    for (int i = t; i < 17 * 16; i += blockDim.x) {
        sWm[i] = Wm[i];
        sWv[i] = Wv[i];
    }
    if (t < 16) { sbm[t] = bm[t]; sbv[t] = bv[t]; }
    __syncthreads();

    int gid = blockIdx.x * blockDim.x + t;      // 0 .. B*N-1, gid = b*N + n
    if (gid >= BB * NN) return;
    int b = gid >> 13;                          // / 8192
    int n = gid & (NN - 1);

    float x  = inputs[gid];
    float xm = x * iwm[0];
    float xv = x * iwv[0];

    // hidden_state: (B, 2*N*H); first half mean, second half var
    const float4* hm4 = reinterpret_cast<const float4*>(
        hidden + (size_t)b * (2 * NN * HH) + (size_t)n * HH);
    const float4* hv4 = reinterpret_cast<const float4*>(
        hidden + (size_t)b * (2 * NN * HH) + (size_t)NN * HH + (size_t)n * HH);

    float hm[16], hv[16];
#pragma unroll
    for (int q = 0; q < 4; ++q) {
        float4 a = hm4[q];
        hm[4*q+0] = a.x; hm[4*q+1] = a.y; hm[4*q+2] = a.z; hm[4*q+3] = a.w;
        float4 c = hv4[q];
        hv[4*q+0] = c.x; hv[4*q+1] = c.y; hv[4*q+2] = c.z; hv[4*q+3] = c.w;
    }

    float cm[16], cv[16];
#pragma unroll
    for (int h = 0; h < 16; ++h) {
        cm[h] = fmaf(xm, sWm[h], sbm[h]);
        cv[h] = fmaf(xv, sWv[h], sbv[h]);
    }
#pragma unroll
    for (int j = 0; j < 16; ++j) {
        float a = hm[j], c = hv[j];
#pragma unroll
        for (int h = 0; h < 16; ++h) {
            cm[h] = fmaf(a, sWm[(1 + j) * 16 + h], cm[h]);
            cv[h] = fmaf(c, sWv[(1 + j) * 16 + h], cv[h]);
        }
    }

    float* pm = g_pm + (size_t)n * COLS + b * HH;
    float* pv = g_pv + (size_t)n * COLS + b * HH;
#pragma unroll
    for (int h = 0; h < 16; ++h) {
        float m = fmaxf(cm[h], 0.0f);
        float v = fmaxf(cv[h], 0.0f);
        float w = expf(-v);           // LAMDA = 1
        pm[h] = m * w;
        pv[h] = v * w * w;
    }
}

// ---------------------------------------------------------------------------
// Kernel B: streaming sparse-skip SpMM.
// One warp per (matrix, row n). Streams the 32 KB lap row with float4 loads
// (pure coalesced DRAM traffic), ballots for nonzeros (~34 per row), and for
// each nonzero does 2 FMAs/lane against the L2-resident pm/pv table.
//   out[b, n, h]      = sum_m lap0[n,m] * pm[m, b*16+h]   (h < 16)
//   out[b, n, 16 + h] = sum_m lap1[n,m] * pv[m, b*16+h]
// ---------------------------------------------------------------------------
__global__ void __launch_bounds__(256)
rtgcn_spmm_kernel(const float* __restrict__ lap0,
                  const float* __restrict__ lap1,
                  float* __restrict__ out) {
    int warpId = threadIdx.x >> 5;
    int lane   = threadIdx.x & 31;
    int task   = blockIdx.x * 8 + warpId;       // 0 .. 2*N-1
    bool isVar = task >= NN;
    int n      = isVar ? task - NN : task;

    const float*  lap = isVar ? lap1 : lap0;
    const float*  P   = isVar ? g_pv : g_pm;
    const float4* row = reinterpret_cast<const float4*>(lap + (size_t)n * NN);

    float acc0 = 0.0f, acc1 = 0.0f;

    // 8192 elements / (32 lanes * 4 per float4) = 64 iterations; unroll 4 to
    // keep 4 independent LDG.128 in flight per warp.
    for (int it = 0; it < 64; it += 4) {
        float4 v[4];
#pragma unroll
        for (int u = 0; u < 4; ++u)
            v[u] = row[(it + u) * 32 + lane];

#pragma unroll
        for (int u = 0; u < 4; ++u) {
            int m0 = (it + u) * 128;
            float vc[4] = {v[u].x, v[u].y, v[u].z, v[u].w};
#pragma unroll
            for (int c = 0; c < 4; ++c) {
                float x = vc[c];
                unsigned mask = __ballot_sync(0xFFFFFFFFu, x != 0.0f);
                while (mask) {
                    int k = __ffs(mask) - 1;
                    mask &= mask - 1;
                    float val = __shfl_sync(0xFFFFFFFFu, x, k);
                    int m = m0 + 4 * k + c;     // lane k holds elements m0+4k+c
                    const float* Pm = P + (size_t)m * COLS;
                    acc0 = fmaf(val, Pm[lane],      acc0);
                    acc1 = fmaf(val, Pm[lane + 32], acc1);
                }
            }
        }
    }

    // Scatter the 64 results. col = b*16 + h. Output (B, N, 2H).
    int h   = lane & 15;
    int b0  = lane >> 4;          // cols  0..31 -> b 0,1
    int b1  = 2 + (lane >> 4);    // cols 32..63 -> b 2,3
    int off = isVar ? HH : 0;
    out[((size_t)b0 * NN + n) * (2 * HH) + off + h] = acc0;
    out[((size_t)b1 * NN + n) * (2 * HH) + off + h] = acc1;
}

// ---------------------------------------------------------------------------
extern "C" void kernel_launch(void* const* d_in, const int* in_sizes, int n_in,
                              void* d_out, int out_size) {
    const float* inputs = (const float*)d_in[0];   // (B, N)
    const float* hidden = (const float*)d_in[1];   // (B, 2*N*H)
    const float* lap0   = (const float*)d_in[2];   // (N, N)
    const float* lap1   = (const float*)d_in[3];   // (N, N)
    const float* Wm     = (const float*)d_in[4];   // (17, 16)
    const float* bm     = (const float*)d_in[5];   // (16,)
    const float* Wv     = (const float*)d_in[6];   // (17, 16)
    const float* bv     = (const float*)d_in[7];   // (16,)
    const float* iwm    = (const float*)d_in[8];   // (1, 1)
    const float* iwv    = (const float*)d_in[9];   // (1, 1)
    float* out          = (float*)d_out;           // (B, N, 2H)

    (void)in_sizes; (void)n_in; (void)out_size;

    // Kernel A: 32768 threads, one per (b, n)
    rtgcn_gate_kernel<<<(BB * NN + 255) / 256, 256>>>(
        inputs, hidden, Wm, bm, Wv, bv, iwm, iwv);

    // Kernel B: one warp per (matrix, row): 2*8192 warps / 8 per block
    rtgcn_spmm_kernel<<<(2 * NN) / 8, 256>>>(lap0, lap1, out);
}

// round 3
// speedup vs baseline: 1.0853x; 1.0853x over previous
#include <cuda_runtime.h>
#include <cstdint>

// Problem constants (fixed by the dataset)
#define NN    8192          // num nodes
#define HH    16            // gru units
#define BB    4             // batch
#define COLS  (BB * HH)     // 64 columns per matrix

// Scratch: gated per-node feature tables, m-major so a warp reads
// P[m*64 + lane] / P[m*64 + lane + 32] as two 128B transactions.
// 2 MB each -> L2-resident during the SpMM stream.
__device__ float g_pm[NN * COLS];
__device__ float g_pv[NN * COLS];

// ---------------------------------------------------------------------------
// Kernel A: gating. One thread per (b, n).
//   cm = relu([x*iwm, h_mean] @ Wm + bm)
//   cv = relu([x*iwv, h_var ] @ Wv + bv)
//   nw = exp(-cv);  pm = cm*nw;  pv = cv*nw*nw
// ---------------------------------------------------------------------------
__global__ void rtgcn_gate_kernel(const float* __restrict__ inputs,
                                  const float* __restrict__ hidden,
                                  const float* __restrict__ Wm,
                                  const float* __restrict__ bm,
                                  const float* __restrict__ Wv,
                                  const float* __restrict__ bv,
                                  const float* __restrict__ iwm,
                                  const float* __restrict__ iwv) {
    __shared__ float sWm[17 * 16];
    __shared__ float sWv[17 * 16];
    __shared__ float sbm[16];
    __shared__ float sbv[16];

    int t = threadIdx.x;
    for (int i = t; i < 17 * 16; i += blockDim.x) {
        sWm[i] = Wm[i];
        sWv[i] = Wv[i];
    }
    if (t < 16) { sbm[t] = bm[t]; sbv[t] = bv[t]; }
    __syncthreads();

    int gid = blockIdx.x * blockDim.x + t;      // gid = b*N + n
    if (gid >= BB * NN) return;
    int b = gid >> 13;
    int n = gid & (NN - 1);

    float x  = inputs[gid];
    float xm = x * iwm[0];
    float xv = x * iwv[0];

    const float4* hm4 = reinterpret_cast<const float4*>(
        hidden + (size_t)b * (2 * NN * HH) + (size_t)n * HH);
    const float4* hv4 = reinterpret_cast<const float4*>(
        hidden + (size_t)b * (2 * NN * HH) + (size_t)NN * HH + (size_t)n * HH);

    float hm[16], hv[16];
#pragma unroll
    for (int q = 0; q < 4; ++q) {
        float4 a = hm4[q];
        hm[4*q+0] = a.x; hm[4*q+1] = a.y; hm[4*q+2] = a.z; hm[4*q+3] = a.w;
        float4 c = hv4[q];
        hv[4*q+0] = c.x; hv[4*q+1] = c.y; hv[4*q+2] = c.z; hv[4*q+3] = c.w;
    }

    float cm[16], cv[16];
#pragma unroll
    for (int h = 0; h < 16; ++h) {
        cm[h] = fmaf(xm, sWm[h], sbm[h]);
        cv[h] = fmaf(xv, sWv[h], sbv[h]);
    }
#pragma unroll
    for (int j = 0; j < 16; ++j) {
        float a = hm[j], c = hv[j];
#pragma unroll
        for (int h = 0; h < 16; ++h) {
            cm[h] = fmaf(a, sWm[(1 + j) * 16 + h], cm[h]);
            cv[h] = fmaf(c, sWv[(1 + j) * 16 + h], cv[h]);
        }
    }

    float* pm = g_pm + (size_t)n * COLS + b * HH;
    float* pv = g_pv + (size_t)n * COLS + b * HH;
#pragma unroll
    for (int h = 0; h < 16; ++h) {
        float m = fmaxf(cm[h], 0.0f);
        float v = fmaxf(cv[h], 0.0f);
        float w = expf(-v);           // LAMDA = 1
        pm[h] = m * w;
        pv[h] = v * w * w;
    }
}

// ---------------------------------------------------------------------------
// Kernel B: streaming sparse-skip SpMM. One warp per (matrix, row n).
// Streams the 32 KB lap row with __ldcs float4 loads (evict-first so the
// 4 MB pm/pv tables stay L2-resident), ONE ballot per float4 group (128
// elements), and resolves the ~34 nonzeros/row with shfl broadcasts +
// warp-uniform per-component branches.
// ---------------------------------------------------------------------------
__global__ void __launch_bounds__(256)
rtgcn_spmm_kernel(const float* __restrict__ lap0,
                  const float* __restrict__ lap1,
                  float* __restrict__ out) {
    int warpId = threadIdx.x >> 5;
    int lane   = threadIdx.x & 31;
    int task   = blockIdx.x * 8 + warpId;       // 0 .. 2*N-1
    bool isVar = task >= NN;
    int n      = isVar ? task - NN : task;

    const float*  lap = isVar ? lap1 : lap0;
    const float*  P   = isVar ? g_pv : g_pm;
    const float4* row = reinterpret_cast<const float4*>(lap + (size_t)n * NN);

    float acc0 = 0.0f, acc1 = 0.0f;

    // 8192 / (32 lanes * 4) = 64 float4-iterations; unroll 8 -> 8 LDG.128
    // outstanding per warp per group.
#pragma unroll 1
    for (int it = 0; it < 64; it += 8) {
        float4 v[8];
#pragma unroll
        for (int u = 0; u < 8; ++u)
            v[u] = __ldcs(&row[(it + u) * 32 + lane]);

#pragma unroll
        for (int u = 0; u < 8; ++u) {
            // one ballot per 128 elements: any of my 4 words nonzero?
            unsigned nz = (__float_as_uint(v[u].x) | __float_as_uint(v[u].y) |
                           __float_as_uint(v[u].z) | __float_as_uint(v[u].w));
            unsigned mask = __ballot_sync(0xFFFFFFFFu, nz != 0u);
            int m0 = (it + u) * 128;
            while (mask) {
                int k = __ffs(mask) - 1;
                mask &= mask - 1;
                float x0 = __shfl_sync(0xFFFFFFFFu, v[u].x, k);
                float x1 = __shfl_sync(0xFFFFFFFFu, v[u].y, k);
                float x2 = __shfl_sync(0xFFFFFFFFu, v[u].z, k);
                float x3 = __shfl_sync(0xFFFFFFFFu, v[u].w, k);
                int mb = m0 + 4 * k;
                // warp-uniform branches (x* broadcast to all lanes)
                if (x0 != 0.0f) {
                    const float* Pm = P + (size_t)mb * COLS;
                    acc0 = fmaf(x0, Pm[lane],      acc0);
                    acc1 = fmaf(x0, Pm[lane + 32], acc1);
                }
                if (x1 != 0.0f) {
                    const float* Pm = P + (size_t)(mb + 1) * COLS;
                    acc0 = fmaf(x1, Pm[lane],      acc0);
                    acc1 = fmaf(x1, Pm[lane + 32], acc1);
                }
                if (x2 != 0.0f) {
                    const float* Pm = P + (size_t)(mb + 2) * COLS;
                    acc0 = fmaf(x2, Pm[lane],      acc0);
                    acc1 = fmaf(x2, Pm[lane + 32], acc1);
                }
                if (x3 != 0.0f) {
                    const float* Pm = P + (size_t)(mb + 3) * COLS;
                    acc0 = fmaf(x3, Pm[lane],      acc0);
                    acc1 = fmaf(x3, Pm[lane + 32], acc1);
                }
            }
        }
    }

    // Scatter the 64 results. col = b*16 + h. Output (B, N, 2H).
    int h   = lane & 15;
    int b0  = lane >> 4;          // cols  0..31 -> b 0,1
    int b1  = 2 + (lane >> 4);    // cols 32..63 -> b 2,3
    int off = isVar ? HH : 0;
    out[((size_t)b0 * NN + n) * (2 * HH) + off + h] = acc0;
    out[((size_t)b1 * NN + n) * (2 * HH) + off + h] = acc1;
}

// ---------------------------------------------------------------------------
extern "C" void kernel_launch(void* const* d_in, const int* in_sizes, int n_in,
                              void* d_out, int out_size) {
    const float* inputs = (const float*)d_in[0];   // (B, N)
    const float* hidden = (const float*)d_in[1];   // (B, 2*N*H)
    const float* lap0   = (const float*)d_in[2];   // (N, N)
    const float* lap1   = (const float*)d_in[3];   // (N, N)
    const float* Wm     = (const float*)d_in[4];   // (17, 16)
    const float* bm     = (const float*)d_in[5];   // (16,)
    const float* Wv     = (const float*)d_in[6];   // (17, 16)
    const float* bv     = (const float*)d_in[7];   // (16,)
    const float* iwm    = (const float*)d_in[8];   // (1, 1)
    const float* iwv    = (const float*)d_in[9];   // (1, 1)
    float* out          = (float*)d_out;           // (B, N, 2H)

    (void)in_sizes; (void)n_in; (void)out_size;

    rtgcn_gate_kernel<<<(BB * NN + 255) / 256, 256>>>(
        inputs, hidden, Wm, bm, Wv, bv, iwm, iwv);

    rtgcn_spmm_kernel<<<(2 * NN) / 8, 256>>>(lap0, lap1, out);
}

// round 4
// speedup vs baseline: 1.1176x; 1.0297x over previous
#include <cuda_runtime.h>
#include <cstdint>

// Problem constants (fixed by the dataset)
#define NN    8192          // num nodes
#define HH    16            // gru units
#define BB    4             // batch
#define COLS  (BB * HH)     // 64 columns per matrix

// Scratch: gated per-node feature tables, m-major so a warp reads
// P[m*64 + lane] / P[m*64 + lane + 32] as two 128B transactions.
// 2 MB each -> L2-resident during the SpMM stream.
__device__ float g_pm[NN * COLS];
__device__ float g_pv[NN * COLS];

// ---------------------------------------------------------------------------
// Kernel A: gating. One thread per (b, n).
//   cm = relu([x*iwm, h_mean] @ Wm + bm)
//   cv = relu([x*iwv, h_var ] @ Wv + bv)
//   nw = exp(-cv);  pm = cm*nw;  pv = cv*nw*nw
// ---------------------------------------------------------------------------
__global__ void rtgcn_gate_kernel(const float* __restrict__ inputs,
                                  const float* __restrict__ hidden,
                                  const float* __restrict__ Wm,
                                  const float* __restrict__ bm,
                                  const float* __restrict__ Wv,
                                  const float* __restrict__ bv,
                                  const float* __restrict__ iwm,
                                  const float* __restrict__ iwv) {
    __shared__ float sWm[17 * 16];
    __shared__ float sWv[17 * 16];
    __shared__ float sbm[16];
    __shared__ float sbv[16];

    int t = threadIdx.x;
    for (int i = t; i < 17 * 16; i += blockDim.x) {
        sWm[i] = Wm[i];
        sWv[i] = Wv[i];
    }
    if (t < 16) { sbm[t] = bm[t]; sbv[t] = bv[t]; }
    __syncthreads();

    int gid = blockIdx.x * blockDim.x + t;      // gid = b*N + n
    if (gid >= BB * NN) return;
    int b = gid >> 13;
    int n = gid & (NN - 1);

    float x  = inputs[gid];
    float xm = x * iwm[0];
    float xv = x * iwv[0];

    const float4* hm4 = reinterpret_cast<const float4*>(
        hidden + (size_t)b * (2 * NN * HH) + (size_t)n * HH);
    const float4* hv4 = reinterpret_cast<const float4*>(
        hidden + (size_t)b * (2 * NN * HH) + (size_t)NN * HH + (size_t)n * HH);

    float hm[16], hv[16];
#pragma unroll
    for (int q = 0; q < 4; ++q) {
        float4 a = hm4[q];
        hm[4*q+0] = a.x; hm[4*q+1] = a.y; hm[4*q+2] = a.z; hm[4*q+3] = a.w;
        float4 c = hv4[q];
        hv[4*q+0] = c.x; hv[4*q+1] = c.y; hv[4*q+2] = c.z; hv[4*q+3] = c.w;
    }

    float cm[16], cv[16];
#pragma unroll
    for (int h = 0; h < 16; ++h) {
        cm[h] = fmaf(xm, sWm[h], sbm[h]);
        cv[h] = fmaf(xv, sWv[h], sbv[h]);
    }
#pragma unroll
    for (int j = 0; j < 16; ++j) {
        float a = hm[j], c = hv[j];
#pragma unroll
        for (int h = 0; h < 16; ++h) {
            cm[h] = fmaf(a, sWm[(1 + j) * 16 + h], cm[h]);
            cv[h] = fmaf(c, sWv[(1 + j) * 16 + h], cv[h]);
        }
    }

    float* pm = g_pm + (size_t)n * COLS + b * HH;
    float* pv = g_pv + (size_t)n * COLS + b * HH;
#pragma unroll
    for (int h = 0; h < 16; ++h) {
        float m = fmaxf(cm[h], 0.0f);
        float v = fmaxf(cv[h], 0.0f);
        float w = expf(-v);           // LAMDA = 1
        pm[h] = m * w;
        pv[h] = v * w * w;
    }
}

// ---------------------------------------------------------------------------
// Kernel B: streaming sparse-skip SpMM. One warp per (matrix, row n).
// Streams the 32 KB lap row with __ldcs float4 loads (evict-first so the
// 4 MB pm/pv tables stay L2-resident), ONE ballot per float4 group (128
// elements), and resolves the ~34 nonzeros/row with shfl broadcasts +
// warp-uniform per-component branches.
// ---------------------------------------------------------------------------
__global__ void __launch_bounds__(256)
rtgcn_spmm_kernel(const float* __restrict__ lap0,
                  const float* __restrict__ lap1,
                  float* __restrict__ out) {
    int warpId = threadIdx.x >> 5;
    int lane   = threadIdx.x & 31;
    int task   = blockIdx.x * 8 + warpId;       // 0 .. 2*N-1
    bool isVar = task >= NN;
    int n      = isVar ? task - NN : task;

    const float*  lap = isVar ? lap1 : lap0;
    const float*  P   = isVar ? g_pv : g_pm;
    const float4* row = reinterpret_cast<const float4*>(lap + (size_t)n * NN);

    float acc0 = 0.0f, acc1 = 0.0f;

    // 8192 / (32 lanes * 4) = 64 float4-iterations; unroll 8 -> 8 LDG.128
    // outstanding per warp per group.
#pragma unroll 1
    for (int it = 0; it < 64; it += 8) {
        float4 v[8];
#pragma unroll
        for (int u = 0; u < 8; ++u)
            v[u] = __ldcs(&row[(it + u) * 32 + lane]);

#pragma unroll
        for (int u = 0; u < 8; ++u) {
            // one ballot per 128 elements: any of my 4 words nonzero?
            unsigned nz = (__float_as_uint(v[u].x) | __float_as_uint(v[u].y) |
                           __float_as_uint(v[u].z) | __float_as_uint(v[u].w));
            unsigned mask = __ballot_sync(0xFFFFFFFFu, nz != 0u);
            int m0 = (it + u) * 128;
            while (mask) {
                int k = __ffs(mask) - 1;
                mask &= mask - 1;
                float x0 = __shfl_sync(0xFFFFFFFFu, v[u].x, k);
                float x1 = __shfl_sync(0xFFFFFFFFu, v[u].y, k);
                float x2 = __shfl_sync(0xFFFFFFFFu, v[u].z, k);
                float x3 = __shfl_sync(0xFFFFFFFFu, v[u].w, k);
                int mb = m0 + 4 * k;
                // warp-uniform branches (x* broadcast to all lanes)
                if (x0 != 0.0f) {
                    const float* Pm = P + (size_t)mb * COLS;
                    acc0 = fmaf(x0, Pm[lane],      acc0);
                    acc1 = fmaf(x0, Pm[lane + 32], acc1);
                }
                if (x1 != 0.0f) {
                    const float* Pm = P + (size_t)(mb + 1) * COLS;
                    acc0 = fmaf(x1, Pm[lane],      acc0);
                    acc1 = fmaf(x1, Pm[lane + 32], acc1);
                }
                if (x2 != 0.0f) {
                    const float* Pm = P + (size_t)(mb + 2) * COLS;
                    acc0 = fmaf(x2, Pm[lane],      acc0);
                    acc1 = fmaf(x2, Pm[lane + 32], acc1);
                }
                if (x3 != 0.0f) {
                    const float* Pm = P + (size_t)(mb + 3) * COLS;
                    acc0 = fmaf(x3, Pm[lane],      acc0);
                    acc1 = fmaf(x3, Pm[lane + 32], acc1);
                }
            }
        }
    }

    // Scatter the 64 results. col = b*16 + h. Output (B, N, 2H).
    int h   = lane & 15;
    int b0  = lane >> 4;          // cols  0..31 -> b 0,1
    int b1  = 2 + (lane >> 4);    // cols 32..63 -> b 2,3
    int off = isVar ? HH : 0;
    out[((size_t)b0 * NN + n) * (2 * HH) + off + h] = acc0;
    out[((size_t)b1 * NN + n) * (2 * HH) + off + h] = acc1;
}

// ---------------------------------------------------------------------------
extern "C" void kernel_launch(void* const* d_in, const int* in_sizes, int n_in,
                              void* d_out, int out_size) {
    const float* inputs = (const float*)d_in[0];   // (B, N)
    const float* hidden = (const float*)d_in[1];   // (B, 2*N*H)
    const float* lap0   = (const float*)d_in[2];   // (N, N)
    const float* lap1   = (const float*)d_in[3];   // (N, N)
    const float* Wm     = (const float*)d_in[4];   // (17, 16)
    const float* bm     = (const float*)d_in[5];   // (16,)
    const float* Wv     = (const float*)d_in[6];   // (17, 16)
    const float* bv     = (const float*)d_in[7];   // (16,)
    const float* iwm    = (const float*)d_in[8];   // (1, 1)
    const float* iwv    = (const float*)d_in[9];   // (1, 1)
    float* out          = (float*)d_out;           // (B, N, 2H)

    (void)in_sizes; (void)n_in; (void)out_size;

    rtgcn_gate_kernel<<<(BB * NN + 255) / 256, 256>>>(
        inputs, hidden, Wm, bm, Wv, bv, iwm, iwv);

    rtgcn_spmm_kernel<<<(2 * NN) / 8, 256>>>(lap0, lap1, out);
}